// round 16
// baseline (speedup 1.0000x reference)
#include <cuda_runtime.h>
#include <cstdint>

#define BATCH 32
#define SEQ   512
#define DIMK  64
#define DPITCH 1024
#define BIGF  1e30f
#define VBIG  1e29f
#define L2E   1.4426950408889634f
#define LN2   0.6931471805599453f

// Diagonal-major distance scratch: Ddiag[b][p][i] = D[b, i, p-i]  (64 MB)
__device__ float g_Ddiag[BATCH * DPITCH * SEQ];

__device__ __forceinline__ float ex2f(float x) {
  float r; asm("ex2.approx.f32 %0, %1;" : "=f"(r) : "f"(x)); return r;
}
__device__ __forceinline__ float lg2f(float x) {
  float r; asm("lg2.approx.f32 %0, %1;" : "=f"(r) : "f"(x)); return r;
}

// ---------------------------------------------------------------------------
// Phase 1: D = x2 + y2 - 2 x.y, diagonal-major output.
// R12 GEMM verbatim (best measured, ~54us): 256 threads, 128x128 tile,
// halves split the 16 j-blocks (8 each), per-half 128x8 staging.
// ---------------------------------------------------------------------------
#define TI 128
#define TJ 128
#define YS_STRIDE 132
#define DST_STRIDE 9

__global__ __launch_bounds__(256) void gemm_diag_kernel(
    const float* __restrict__ X, const float* __restrict__ Y) {
  const int t    = threadIdx.x;
  const int half = t >> 7;
  const int tt   = t & 127;
  const int i0 = blockIdx.x * TI;
  const int j0 = blockIdx.y * TJ;
  const int b  = blockIdx.z;

  __shared__ float Ys[DIMK * YS_STRIDE];     // [k][j]
  __shared__ float y2s[TJ];
  __shared__ float Dst[2][TI * DST_STRIDE];  // per-half staging

  const float* Xb = X + ((size_t)b * SEQ + i0) * DIMK;
  const float* Yb = Y + ((size_t)b * SEQ + j0) * DIMK;

  for (int e = t; e < TJ * DIMK; e += 256) {
    int j = e >> 6;
    int k = e & 63;
    Ys[k * YS_STRIDE + j] = Yb[e];
  }

  float xr[DIMK];
  float x2 = 0.f;
#pragma unroll
  for (int k4 = 0; k4 < DIMK; k4 += 4) {
    float4 v = *reinterpret_cast<const float4*>(Xb + (size_t)tt * DIMK + k4);
    xr[k4] = v.x; xr[k4 + 1] = v.y; xr[k4 + 2] = v.z; xr[k4 + 3] = v.w;
  }
#pragma unroll
  for (int k = 0; k < DIMK; k++) x2 += xr[k] * xr[k];

  __syncthreads();

  if (half == 0) {
    float a = 0.f;
#pragma unroll
    for (int k = 0; k < DIMK; k++) {
      float yv = Ys[k * YS_STRIDE + tt];
      a += yv * yv;
    }
    y2s[tt] = a;
  }
  __syncthreads();

  float* gout = g_Ddiag + (size_t)b * (DPITCH * SEQ);
  const int w = tt >> 5, lane = tt & 31;

  for (int jj = 0; jj < 8; jj++) {
    const int jb = half * 8 + jj;
    float acc[8];
#pragma unroll
    for (int m = 0; m < 8; m++) acc[m] = 0.f;

#pragma unroll
    for (int k = 0; k < DIMK; k++) {
      const float4 ya = *reinterpret_cast<const float4*>(&Ys[k * YS_STRIDE + jb * 8]);
      const float4 yb = *reinterpret_cast<const float4*>(&Ys[k * YS_STRIDE + jb * 8 + 4]);
      const float xv = xr[k];
      acc[0] += xv * ya.x; acc[1] += xv * ya.y;
      acc[2] += xv * ya.z; acc[3] += xv * ya.w;
      acc[4] += xv * yb.x; acc[5] += xv * yb.y;
      acc[6] += xv * yb.z; acc[7] += xv * yb.w;
    }

#pragma unroll
    for (int m = 0; m < 8; m++) {
      Dst[half][tt * DST_STRIDE + m] = x2 + y2s[jb * 8 + m] - 2.f * acc[m];
    }
    __syncthreads();

    const int p0 = i0 + j0 + jb * 8;
    for (int dbase = w * 4; dbase < TI + 8 - 1; dbase += 16) {
      int d = dbase + (lane >> 3);
      int q = lane & 7;
      if (d < TI + 8 - 1) {
        int lo = d - 7 < 0 ? 0 : d - 7;
        int hi = d < TI - 1 ? d : TI - 1;
        int irow = lo + q;
        if (irow <= hi) {
          gout[(size_t)(p0 + d) * SEQ + (i0 + irow)] =
              Dst[half][irow * DST_STRIDE + (d - irow)];
        }
      }
    }
    __syncthreads();
  }
}

// ---------------------------------------------------------------------------
// Phase 2: wavefront DP — R12 structure (4 warps, 4 rows/thread, parity
// mailboxes, barrier/step, 8-deep float4 prefetch) with an EXACT
// warp-uniform softmin fast path: when every cell in the warp has
// med-min >= 25 (=> 1 + e1 + e2 == 1.0f exactly) or is an invalid all-BIG
// cell, softmin == min and the 2xEX2 + LG2 tail is skipped entirely.
// Base-2 scaled domain (R' = R * log2e).
// ---------------------------------------------------------------------------
__global__ __launch_bounds__(128) void softdtw_dp_kernel(float* __restrict__ out) {
  const int b = blockIdx.x;
  const int t = threadIdx.x;
  const int lane = t & 31, w = t >> 5;

  __shared__ float sb1[2][4];
  __shared__ float sb2[2][4];
  if (t < 8) {
    (&sb1[0][0])[t] = BIGF;
    (&sb2[0][0])[t] = BIGF;
  }

  float v1[4], v2[4];
#pragma unroll
  for (int k = 0; k < 4; k++) { v1[k] = BIGF; v2[k] = BIGF; }

  const float* base = g_Ddiag + (size_t)b * (DPITCH * SEQ) + 4 * t;
  __syncthreads();

  // min/med/max of (a,b,c); then softmin = mn - lg2(1 + 2^(mn-md) + 2^(mn-mx))
#define MMM(A, B, C, MN, MD, MX)                                              \
  {                                                                           \
    float u_ = fminf((A), (B)), v_ = fmaxf((A), (B));                         \
    MN = fminf(u_, (C));                                                      \
    MX = fmaxf(v_, (C));                                                      \
    MD = fmaxf(u_, fminf(v_, (C)));                                           \
  }

#define DP_STEP(P, G4)                                                        \
  {                                                                           \
    const int rs = (P) & 1;                                                   \
    float nb1 = __shfl_up_sync(0xffffffffu, v1[3], 1);                        \
    float nb2 = __shfl_up_sync(0xffffffffu, v2[3], 1);                        \
    if (lane == 0) {                                                          \
      nb1 = (w == 0) ? BIGF : sb1[rs][w - 1];                                 \
      nb2 = (w == 0) ? (((P) == 0) ? 0.0f : BIGF) : sb2[rs][w - 1];           \
    }                                                                         \
    float mn0, md0, mx0, mn1, md1, mx1, mn2, md2, mx2, mn3, md3, mx3;         \
    MMM(nb2,   nb1,   v1[0], mn0, md0, mx0);                                  \
    MMM(v2[0], v1[0], v1[1], mn1, md1, mx1);                                  \
    MMM(v2[1], v1[1], v1[2], mn2, md2, mx2);                                  \
    MMM(v2[2], v1[2], v1[3], mn3, md3, mx3);                                  \
    float sm0 = mn0, sm1 = mn1, sm2 = mn2, sm3 = mn3;                         \
    int need = ((md0 - mn0 < 25.0f) && (mn0 < VBIG)) ||                       \
               ((md1 - mn1 < 25.0f) && (mn1 < VBIG)) ||                       \
               ((md2 - mn2 < 25.0f) && (mn2 < VBIG)) ||                       \
               ((md3 - mn3 < 25.0f) && (mn3 < VBIG));                         \
    if (__ballot_sync(0xffffffffu, need) != 0u) {                             \
      sm0 = mn0 - lg2f(1.0f + ex2f(mn0 - md0) + ex2f(mn0 - mx0));             \
      sm1 = mn1 - lg2f(1.0f + ex2f(mn1 - md1) + ex2f(mn1 - mx1));             \
      sm2 = mn2 - lg2f(1.0f + ex2f(mn2 - md2) + ex2f(mn2 - mx2));             \
      sm3 = mn3 - lg2f(1.0f + ex2f(mn3 - md3) + ex2f(mn3 - mx3));             \
    }                                                                         \
    unsigned pr = (unsigned)((P) - 4 * t);                                    \
    float n0 = (pr      < (unsigned)SEQ) ? fmaf((G4).x, L2E, sm0) : BIGF;     \
    float n1 = (pr - 1u < (unsigned)SEQ) ? fmaf((G4).y, L2E, sm1) : BIGF;     \
    float n2 = (pr - 2u < (unsigned)SEQ) ? fmaf((G4).z, L2E, sm2) : BIGF;     \
    float n3 = (pr - 3u < (unsigned)SEQ) ? fmaf((G4).w, L2E, sm3) : BIGF;     \
    v2[0] = v1[0]; v2[1] = v1[1]; v2[2] = v1[2]; v2[3] = v1[3];               \
    v1[0] = n0;    v1[1] = n1;    v1[2] = n2;    v1[3] = n3;                  \
    if (lane == 31) { sb1[rs ^ 1][w] = v1[3]; sb2[rs ^ 1][w] = v2[3]; }       \
    __syncthreads();                                                          \
  }

  // prefetch pipeline: groups of 8 diagonals
  float4 cur[8];
#pragma unroll
  for (int j = 0; j < 8; j++)
    cur[j] = *reinterpret_cast<const float4*>(base + (size_t)j * SEQ);

  for (int g = 0; g < 127; ++g) {
    float4 nxt[8];
#pragma unroll
    for (int j = 0; j < 8; j++)
      nxt[j] = *reinterpret_cast<const float4*>(base + (size_t)(8 * (g + 1) + j) * SEQ);
#pragma unroll
    for (int j = 0; j < 8; j++) {
      const int p = 8 * g + j;
      DP_STEP(p, cur[j]);
    }
#pragma unroll
    for (int j = 0; j < 8; j++) cur[j] = nxt[j];
  }
  // epilogue: p = 1016 .. 1022
#pragma unroll
  for (int j = 0; j < 7; j++) {
    const int p = 1016 + j;
    DP_STEP(p, cur[j]);
  }

  if (t == 127) out[b] = v1[3] * LN2;  // R(511,511), back to nat domain
#undef DP_STEP
#undef MMM
}

// ---------------------------------------------------------------------------
extern "C" void kernel_launch(void* const* d_in, const int* in_sizes, int n_in,
                              void* d_out, int out_size) {
  const float* X = (const float*)d_in[0];
  const float* Y = (const float*)d_in[1];
  float* out = (float*)d_out;

  dim3 grid_g(SEQ / TI, SEQ / TJ, BATCH);
  gemm_diag_kernel<<<grid_g, 256>>>(X, Y);
  softdtw_dp_kernel<<<BATCH, 128>>>(out);
}

// round 17
// speedup vs baseline: 1.5952x; 1.5952x over previous
#include <cuda_runtime.h>
#include <cstdint>

#define BATCH 32
#define SEQ   512
#define DIMK  64
#define DPITCH 1024
#define BIGF  1e30f
#define L2E   1.4426950408889634f
#define LN2   0.6931471805599453f

#define NLEVEL  28       // anti-diagonal levels of 32 diagonals
#define NTILE   2048     // 32 batches * 4 i-tiles * 16 j-tiles (128x32 tiles)

__device__ float g_Ddiag[BATCH * DPITCH * SEQ];
__device__ int g_cnt[BATCH * NLEVEL];

__global__ void zero_cnt_kernel() {
  int t = threadIdx.x;
  if (t < BATCH * NLEVEL) g_cnt[t] = 0;
}

// tiles per batch at level L (i0 in {0,128,256,384}, j0 in {0,32,...,480})
__device__ __forceinline__ int cL(int L) {
  int vimax = L >> 2; if (vimax > 3) vimax = 3;
  int vimin = (L - 12) >> 2; if (vimin < 0) vimin = 0;
  return vimax - vimin + 1;
}

__device__ __forceinline__ int ld_acq(const int* p) {
  int v;
  asm volatile("ld.acquire.gpu.global.b32 %0, [%1];" : "=r"(v) : "l"(p) : "memory");
  return v;
}

__device__ __forceinline__ float ex2f(float x) {
  float r; asm("ex2.approx.f32 %0, %1;" : "=f"(r) : "f"(x)); return r;
}
__device__ __forceinline__ float lg2f(float x) {
  float r; asm("lg2.approx.f32 %0, %1;" : "=f"(r) : "f"(x)); return r;
}
__device__ __forceinline__ float softmin3s(float a, float b, float c) {
  float u = fminf(a, b), v = fmaxf(a, b);
  float mn = fminf(u, c);
  float mx = fmaxf(v, c);
  float md = fmaxf(u, fminf(v, c));
  float s = 1.0f + ex2f(mn - md) + ex2f(mn - mx);
  return mn - lg2f(s);
}

// ---------------------------------------------------------------------------
// GEMM worker role: ONE 128(i) x 32(j) tile per CTA; bid order == priority
// order. R9 body; DST_STRIDE 34 => staging reads conflict-free (i*33 + d).
// ---------------------------------------------------------------------------
#define YS_STRIDE 36
#define DST_STRIDE 34

__device__ void gemm_worker(const float* __restrict__ X,
                            const float* __restrict__ Y, int q) {
  __shared__ float Ys[DIMK * YS_STRIDE];
  __shared__ float y2s[32];
  __shared__ float Dst[128 * DST_STRIDE];

  const int t = threadIdx.x;
  const int w = t >> 5, lane = t & 31;

  // decode priority index q -> (L, k, b) -> (b, i0, j0)
  int qq = q, L = 0;
  for (;;) {
    int blk = 32 * cL(L);
    if (qq < blk) break;
    qq -= blk; L++;
  }
  const int k_in = qq >> 5;
  const int b = qq & 31;
  int vimin = (L - 12) >> 2; if (vimin < 0) vimin = 0;
  const int vi = vimin + k_in;
  const int i0 = vi << 7;
  const int j0 = (L - (vi << 2)) << 5;

  const float* Xb = X + ((size_t)b * SEQ + i0) * DIMK;
  const float* Yb = Y + ((size_t)b * SEQ + j0) * DIMK;

  for (int e = t; e < 32 * DIMK; e += 128) {
    int j = e >> 6;
    int kk = e & 63;
    Ys[kk * YS_STRIDE + j] = Yb[e];
  }

  float xr[DIMK];
  float x2 = 0.f;
#pragma unroll
  for (int k4 = 0; k4 < DIMK; k4 += 4) {
    float4 v = *reinterpret_cast<const float4*>(Xb + (size_t)t * DIMK + k4);
    xr[k4] = v.x; xr[k4 + 1] = v.y; xr[k4 + 2] = v.z; xr[k4 + 3] = v.w;
  }
#pragma unroll
  for (int kk = 0; kk < DIMK; kk++) x2 += xr[kk] * xr[kk];

  __syncthreads();

  if (t < 32) {
    float a = 0.f;
#pragma unroll
    for (int kk = 0; kk < DIMK; kk++) {
      float yv = Ys[kk * YS_STRIDE + t];
      a += yv * yv;
    }
    y2s[t] = a;
  }
  __syncthreads();

  for (int jb = 0; jb < 4; jb++) {
    float acc[8];
#pragma unroll
    for (int m = 0; m < 8; m++) acc[m] = 0.f;
#pragma unroll
    for (int kk = 0; kk < DIMK; kk++) {
      const float4 ya = *reinterpret_cast<const float4*>(&Ys[kk * YS_STRIDE + jb * 8]);
      const float4 yb = *reinterpret_cast<const float4*>(&Ys[kk * YS_STRIDE + jb * 8 + 4]);
      const float xv = xr[kk];
      acc[0] += xv * ya.x; acc[1] += xv * ya.y;
      acc[2] += xv * ya.z; acc[3] += xv * ya.w;
      acc[4] += xv * yb.x; acc[5] += xv * yb.y;
      acc[6] += xv * yb.z; acc[7] += xv * yb.w;
    }
#pragma unroll
    for (int m = 0; m < 8; m++) {
      Dst[t * DST_STRIDE + jb * 8 + m] = x2 + y2s[jb * 8 + m] - 2.f * acc[m];
    }
  }
  __syncthreads();

  float* gout = g_Ddiag + (size_t)b * (DPITCH * SEQ);
  const int p0 = i0 + j0;
  for (int d = w; d < 128 + 32 - 1; d += 4) {
    int lo = d - 31 > 0 ? d - 31 : 0;
    int hi = d < 127 ? d : 127;
    int i = lo + lane;
    if (i <= hi) {
      gout[(size_t)(p0 + d) * SEQ + (i0 + i)] =
          Dst[i * DST_STRIDE + (d - i)];
    }
  }
  __syncthreads();

  if (t == 0) {
    __threadfence();
    atomicAdd(&g_cnt[b * NLEVEL + L], 1);
  }
}

// ---------------------------------------------------------------------------
// DP role: R12 wavefront DP, SEGMENTED — 16 segments of 8 prefetch groups;
// level polls only BETWEEN segments so the hot loop compiles like R12's.
// ---------------------------------------------------------------------------
__device__ void dp_role(float* __restrict__ out, int b) {
  const int t = threadIdx.x;
  const int lane = t & 31, w = t >> 5;

  __shared__ float sb1[2][4];
  __shared__ float sb2[2][4];
  if (t < 8) {
    (&sb1[0][0])[t] = BIGF;
    (&sb2[0][0])[t] = BIGF;
  }

  float v1[4], v2[4];
#pragma unroll
  for (int k = 0; k < 4; k++) { v1[k] = BIGF; v2[k] = BIGF; }

  const float* base = g_Ddiag + (size_t)b * (DPITCH * SEQ) + 4 * t;
  const int* cnt = &g_cnt[b * NLEVEL];
  int Ldone = -1;
  __syncthreads();

#define DP_WAIT(LNEED)                                                        \
  {                                                                           \
    int Ln = (LNEED);                                                         \
    if (Ln > 27) Ln = 27;                                                     \
    if (Ln > Ldone) {                                                         \
      if (t == 0) {                                                           \
        for (int L_ = Ldone + 1; L_ <= Ln; ++L_) {                            \
          int tgt = cL(L_);                                                   \
          while (ld_acq(cnt + L_) < tgt) __nanosleep(64);                     \
        }                                                                     \
        __threadfence();                                                      \
      }                                                                       \
      __syncthreads();                                                        \
      Ldone = Ln;                                                             \
    }                                                                         \
  }

#define DP_STEP(P, G4)                                                        \
  {                                                                           \
    const int rs = (P) & 1;                                                   \
    float nb1 = __shfl_up_sync(0xffffffffu, v1[3], 1);                        \
    float nb2 = __shfl_up_sync(0xffffffffu, v2[3], 1);                        \
    if (lane == 0) {                                                          \
      nb1 = (w == 0) ? BIGF : sb1[rs][w - 1];                                 \
      nb2 = (w == 0) ? (((P) == 0) ? 0.0f : BIGF) : sb2[rs][w - 1];           \
    }                                                                         \
    float sm0 = softmin3s(nb2,   nb1,   v1[0]);                               \
    float sm1 = softmin3s(v2[0], v1[0], v1[1]);                               \
    float sm2 = softmin3s(v2[1], v1[1], v1[2]);                               \
    float sm3 = softmin3s(v2[2], v1[2], v1[3]);                               \
    unsigned pr = (unsigned)((P) - 4 * t);                                    \
    float n0 = (pr      < (unsigned)SEQ) ? fmaf((G4).x, L2E, sm0) : BIGF;     \
    float n1 = (pr - 1u < (unsigned)SEQ) ? fmaf((G4).y, L2E, sm1) : BIGF;     \
    float n2 = (pr - 2u < (unsigned)SEQ) ? fmaf((G4).z, L2E, sm2) : BIGF;     \
    float n3 = (pr - 3u < (unsigned)SEQ) ? fmaf((G4).w, L2E, sm3) : BIGF;     \
    v2[0] = v1[0]; v2[1] = v1[1]; v2[2] = v1[2]; v2[3] = v1[3];               \
    v1[0] = n0;    v1[1] = n1;    v1[2] = n2;    v1[3] = n3;                  \
    if (lane == 31) { sb1[rs ^ 1][w] = v1[3]; sb2[rs ^ 1][w] = v2[3]; }       \
    __syncthreads();                                                          \
  }

#define LOADD(G, DST)                                                         \
  {                                                                           \
    _Pragma("unroll") for (int j_ = 0; j_ < 8; j_++) {                        \
      int p_ = 8 * (G) + j_; if (p_ > 1022) p_ = 1022;                        \
      (DST)[j_] = *reinterpret_cast<const float4*>(base + (size_t)p_ * SEQ);  \
    }                                                                         \
  }

#define DP_GROUP_BODY(G)                                                      \
  {                                                                           \
    float4 nxt[8];                                                            \
    LOADD((G) + 1, nxt);                                                      \
    _Pragma("unroll") for (int j = 0; j < 8; j++) {                           \
      const int p = 8 * (G) + j;                                              \
      DP_STEP(p, cur[j]);                                                     \
    }                                                                         \
    _Pragma("unroll") for (int j = 0; j < 8; j++) cur[j] = nxt[j];            \
  }

  float4 cur[8];
  DP_WAIT(0);
  LOADD(0, cur);

  // segments 0..14: 8 groups each; poll only between segments
  for (int seg = 0; seg < 15; ++seg) {
    DP_WAIT(2 * seg + 2);
#pragma unroll 1
    for (int gg = 0; gg < 8; ++gg) {
      const int g = 8 * seg + gg;
      DP_GROUP_BODY(g);
    }
  }
  // segment 15: groups 120..126, then epilogue
  DP_WAIT(27);
#pragma unroll 1
  for (int g = 120; g < 127; ++g) {
    DP_GROUP_BODY(g);
  }
#pragma unroll
  for (int j = 0; j < 7; j++) {
    const int p = 1016 + j;
    DP_STEP(p, cur[j]);
  }

  if (t == 127) out[b] = v1[3] * LN2;   // R(511,511), back to nat domain
#undef DP_STEP
#undef LOADD
#undef DP_WAIT
#undef DP_GROUP_BODY
}

// ---------------------------------------------------------------------------
__global__ __launch_bounds__(128) void fused_kernel(
    const float* __restrict__ X, const float* __restrict__ Y,
    float* __restrict__ out) {
  if (blockIdx.x < BATCH) {
    dp_role(out, blockIdx.x);          // bids 0..31: resident in wave 1
  } else {
    gemm_worker(X, Y, blockIdx.x - BATCH);  // bid order == priority order
  }
}

// ---------------------------------------------------------------------------
extern "C" void kernel_launch(void* const* d_in, const int* in_sizes, int n_in,
                              void* d_out, int out_size) {
  const float* X = (const float*)d_in[0];
  const float* Y = (const float*)d_in[1];
  float* out = (float*)d_out;

  zero_cnt_kernel<<<1, BATCH * NLEVEL>>>();
  fused_kernel<<<BATCH + NTILE, 128>>>(X, Y, out);
}